// round 1
// baseline (speedup 1.0000x reference)
#include <cuda_runtime.h>
#include <cuda_bf16.h>
#include <math.h>

// Problem constants
#define BB 4096     // batch
#define CC 1000     // classes
#define DD 128      // feature dim
#define QQ 65536    // queue length
#define PROTO_M 0.99f

// ---- output layout (flat float32 concat, reference return order) ----
// classfy_out   [B,C]        off 0
// cluster_out   [B,C]        off 4,096,000
// cont_features [2B+Q, D]    off 8,192,000
// cont_labels   [2B+Q]       off 17,629,184
// new_prototypes[C,D]        off 17,702,912
// new_queue     [Q,D]        off 17,830,912
// new_queue_ps  [Q]          off 26,219,520
// new_ptr       [1]          off 26,285,056
static const size_t OFF_CLASSFY = 0;
static const size_t OFF_CLUSTER = (size_t)BB * CC;
static const size_t OFF_CONTF   = OFF_CLUSTER + (size_t)BB * CC;
static const size_t OFF_CONTL   = OFF_CONTF + (size_t)(2 * BB + QQ) * DD;
static const size_t OFF_PROTO   = OFF_CONTL + (size_t)(2 * BB + QQ);
static const size_t OFF_QUEUE   = OFF_PROTO + (size_t)CC * DD;
static const size_t OFF_QP      = OFF_QUEUE + (size_t)QQ * DD;
static const size_t OFF_PTR     = OFF_QP + (size_t)QQ;

// scratch (no allocations allowed -> device globals)
__device__ float g_logits[(size_t)BB * CC];
__device__ int   g_labels[BB];

// ---------------------------------------------------------------------------
// Kernel 1: classfy softmax + argmax(softmax * plabel)
// one block per row, 256 threads, row kept in registers (4 elems/thread)
// ---------------------------------------------------------------------------
__global__ __launch_bounds__(256) void classfy_kernel(
    const float* __restrict__ logits, const float* __restrict__ plabel,
    float* __restrict__ out, int* __restrict__ labels)
{
    const int b = blockIdx.x;
    const int tid = threadIdx.x;
    const float* row = logits + (size_t)b * CC;
    const float* prow = plabel + (size_t)b * CC;
    float* orow = out + (size_t)b * CC;

    float l[4];
    float mx = -1e30f;
#pragma unroll
    for (int j = 0; j < 4; j++) {
        int c = j * 256 + tid;
        l[j] = (c < CC) ? row[c] : -1e30f;
        mx = fmaxf(mx, l[j]);
    }
    // block max
    __shared__ float s0[8];
    __shared__ float s1[8];
    __shared__ float sv[8];
    __shared__ int   si[8];
#pragma unroll
    for (int o = 16; o; o >>= 1) mx = fmaxf(mx, __shfl_xor_sync(0xffffffffu, mx, o));
    if ((tid & 31) == 0) s0[tid >> 5] = mx;
    __syncthreads();
    if (tid < 32) {
        float v = (tid < 8) ? s0[tid] : -1e30f;
#pragma unroll
        for (int o = 4; o; o >>= 1) v = fmaxf(v, __shfl_xor_sync(0xffffffffu, v, o));
        if (tid == 0) s0[0] = v;
    }
    __syncthreads();
    mx = s0[0];

    float e[4];
    float sum = 0.f;
#pragma unroll
    for (int j = 0; j < 4; j++) { e[j] = __expf(l[j] - mx); sum += e[j]; }
#pragma unroll
    for (int o = 16; o; o >>= 1) sum += __shfl_xor_sync(0xffffffffu, sum, o);
    if ((tid & 31) == 0) s1[tid >> 5] = sum;
    __syncthreads();
    if (tid < 32) {
        float v = (tid < 8) ? s1[tid] : 0.f;
#pragma unroll
        for (int o = 4; o; o >>= 1) v += __shfl_xor_sync(0xffffffffu, v, o);
        if (tid == 0) s1[0] = v;
    }
    __syncthreads();
    const float inv = 1.0f / s1[0];

    float bv = -1.0f;
    int bi = 0x7fffffff;
#pragma unroll
    for (int j = 0; j < 4; j++) {
        int c = j * 256 + tid;
        if (c < CC) {
            float o = e[j] * inv;
            orow[c] = o;
            float v = o * prow[c];
            if (v > bv) { bv = v; bi = c; }   // strict > keeps first (c ascending)
        }
    }
    // block argmax, tie -> smaller index (matches jnp.argmax)
#pragma unroll
    for (int o = 16; o; o >>= 1) {
        float ov = __shfl_xor_sync(0xffffffffu, bv, o);
        int   oi = __shfl_xor_sync(0xffffffffu, bi, o);
        if (ov > bv || (ov == bv && oi < bi)) { bv = ov; bi = oi; }
    }
    if ((tid & 31) == 0) { sv[tid >> 5] = bv; si[tid >> 5] = bi; }
    __syncthreads();
    if (tid < 32) {
        float v = (tid < 8) ? sv[tid] : -1.0f;
        int   i = (tid < 8) ? si[tid] : 0x7fffffff;
#pragma unroll
        for (int o = 4; o; o >>= 1) {
            float ov = __shfl_xor_sync(0xffffffffu, v, o);
            int   oi = __shfl_xor_sync(0xffffffffu, i, o);
            if (ov > v || (ov == v && oi < i)) { v = ov; i = oi; }
        }
        if (tid == 0) labels[b] = i;
    }
}

// ---------------------------------------------------------------------------
// Kernel 2: logits_prot = q @ prototypes^T  (M=4096, N=1000, K=128) fp32 tiled
// BM=64, BN=64, BK=64, 256 threads, 4x4 microtile
// ---------------------------------------------------------------------------
#define GBM 64
#define GBN 64
#define GBK 64
__global__ __launch_bounds__(256) void gemm_kernel(
    const float* __restrict__ Aq, const float* __restrict__ Bp,
    float* __restrict__ Cout)
{
    __shared__ __align__(16) float As[GBM][GBK + 4];  // +4 pad keeps 16B align, breaks bank stride
    __shared__ __align__(16) float Bs[GBN][GBK + 4];

    const int tid = threadIdx.x;
    const int tx = tid & 15;   // n micro
    const int ty = tid >> 4;   // m micro
    const int m0 = blockIdx.y * GBM;
    const int n0 = blockIdx.x * GBN;

    float acc[4][4];
#pragma unroll
    for (int i = 0; i < 4; i++)
#pragma unroll
        for (int j = 0; j < 4; j++) acc[i][j] = 0.f;

    for (int kk = 0; kk < DD; kk += GBK) {
#pragma unroll
        for (int p = 0; p < 4; p++) {
            int idx = p * 256 + tid;     // 0..1023 float4 slots (64 rows x 16 f4)
            int r = idx >> 4;
            int c4 = idx & 15;
            float4 va = *(const float4*)(Aq + (size_t)(m0 + r) * DD + kk + c4 * 4);
            *(float4*)&As[r][c4 * 4] = va;
            int n = n0 + r;
            float4 vb = make_float4(0.f, 0.f, 0.f, 0.f);
            if (n < CC) vb = *(const float4*)(Bp + (size_t)n * DD + kk + c4 * 4);
            *(float4*)&Bs[r][c4 * 4] = vb;
        }
        __syncthreads();
#pragma unroll
        for (int k = 0; k < GBK; k++) {
            float a0 = As[ty * 4 + 0][k];
            float a1 = As[ty * 4 + 1][k];
            float a2 = As[ty * 4 + 2][k];
            float a3 = As[ty * 4 + 3][k];
            float b0 = Bs[tx * 4 + 0][k];
            float b1 = Bs[tx * 4 + 1][k];
            float b2 = Bs[tx * 4 + 2][k];
            float b3 = Bs[tx * 4 + 3][k];
            acc[0][0] += a0 * b0; acc[0][1] += a0 * b1; acc[0][2] += a0 * b2; acc[0][3] += a0 * b3;
            acc[1][0] += a1 * b0; acc[1][1] += a1 * b1; acc[1][2] += a1 * b2; acc[1][3] += a1 * b3;
            acc[2][0] += a2 * b0; acc[2][1] += a2 * b1; acc[2][2] += a2 * b2; acc[2][3] += a2 * b3;
            acc[3][0] += a3 * b0; acc[3][1] += a3 * b1; acc[3][2] += a3 * b2; acc[3][3] += a3 * b3;
        }
        __syncthreads();
    }
#pragma unroll
    for (int i = 0; i < 4; i++) {
        int m = m0 + ty * 4 + i;
        float* o = Cout + (size_t)m * CC + n0 + tx * 4;
#pragma unroll
        for (int j = 0; j < 4; j++) {
            if (n0 + tx * 4 + j < CC) o[j] = acc[i][j];
        }
    }
}

// ---------------------------------------------------------------------------
// Kernel 3: cluster softmax (plain row softmax of scratch logits)
// ---------------------------------------------------------------------------
__global__ __launch_bounds__(256) void cluster_softmax_kernel(
    const float* __restrict__ logits, float* __restrict__ out)
{
    const int b = blockIdx.x;
    const int tid = threadIdx.x;
    const float* row = logits + (size_t)b * CC;
    float* orow = out + (size_t)b * CC;

    float l[4];
    float mx = -1e30f;
#pragma unroll
    for (int j = 0; j < 4; j++) {
        int c = j * 256 + tid;
        l[j] = (c < CC) ? row[c] : -1e30f;
        mx = fmaxf(mx, l[j]);
    }
    __shared__ float s0[8];
    __shared__ float s1[8];
#pragma unroll
    for (int o = 16; o; o >>= 1) mx = fmaxf(mx, __shfl_xor_sync(0xffffffffu, mx, o));
    if ((tid & 31) == 0) s0[tid >> 5] = mx;
    __syncthreads();
    if (tid < 32) {
        float v = (tid < 8) ? s0[tid] : -1e30f;
#pragma unroll
        for (int o = 4; o; o >>= 1) v = fmaxf(v, __shfl_xor_sync(0xffffffffu, v, o));
        if (tid == 0) s0[0] = v;
    }
    __syncthreads();
    mx = s0[0];

    float e[4];
    float sum = 0.f;
#pragma unroll
    for (int j = 0; j < 4; j++) { e[j] = __expf(l[j] - mx); sum += e[j]; }
#pragma unroll
    for (int o = 16; o; o >>= 1) sum += __shfl_xor_sync(0xffffffffu, sum, o);
    if ((tid & 31) == 0) s1[tid >> 5] = sum;
    __syncthreads();
    if (tid < 32) {
        float v = (tid < 8) ? s1[tid] : 0.f;
#pragma unroll
        for (int o = 4; o; o >>= 1) v += __shfl_xor_sync(0xffffffffu, v, o);
        if (tid == 0) s1[0] = v;
    }
    __syncthreads();
    const float inv = 1.0f / s1[0];
#pragma unroll
    for (int j = 0; j < 4; j++) {
        int c = j * 256 + tid;
        if (c < CC) orow[c] = e[j] * inv;
    }
}

// ---------------------------------------------------------------------------
// Kernel 4: prototype scatter-EMA + l2norm. One block (128 thr) per class.
// Ordered match list built in parallel (thread t scans samples [32t, 32t+32)).
// ---------------------------------------------------------------------------
__global__ __launch_bounds__(128) void proto_kernel(
    const float* __restrict__ q, const float* __restrict__ protos,
    const int* __restrict__ labels, float* __restrict__ out)
{
    const int c = blockIdx.x;
    const int t = threadIdx.x;

    __shared__ int counts[128];
    __shared__ int offs[128];
    __shared__ int idxbuf[BB];
    __shared__ int total_s;
    __shared__ float ws[4];

    const int base = t * 32;
    int cnt = 0;
#pragma unroll 8
    for (int j = 0; j < 32; j++) if (__ldg(&labels[base + j]) == c) cnt++;
    counts[t] = cnt;
    __syncthreads();
    if (t == 0) {
        int run = 0;
        for (int u = 0; u < 128; u++) { offs[u] = run; run += counts[u]; }
        total_s = run;
    }
    __syncthreads();
    int w = offs[t];
#pragma unroll 8
    for (int j = 0; j < 32; j++) {
        int i = base + j;
        if (__ldg(&labels[i]) == c) idxbuf[w++] = i;
    }
    __syncthreads();
    const int total = total_s;

    float acc = protos[(size_t)c * DD + t];
    for (int j = 0; j < total; j++) {
        acc = PROTO_M * acc + (1.0f - PROTO_M) * q[(size_t)idxbuf[j] * DD + t];
    }
    float s = acc * acc;
#pragma unroll
    for (int o = 16; o; o >>= 1) s += __shfl_xor_sync(0xffffffffu, s, o);
    if ((t & 31) == 0) ws[t >> 5] = s;
    __syncthreads();
    float tot = ws[0] + ws[1] + ws[2] + ws[3];
    float nrm = sqrtf(tot);
    float inv = 1.0f / fmaxf(nrm, 1e-12f);
    out[(size_t)c * DD + t] = acc * inv;
}

// ---------------------------------------------------------------------------
// Kernel 5: epilogue scatter — k rows into new_queue at ptr, labels into
// cont_labels and new_queue_pseudo, new_ptr.
// ---------------------------------------------------------------------------
__device__ __forceinline__ int load_ptr_val(const void* p)
{
    int iv = *(const int*)p;
    if (iv >= 0 && iv <= QQ) return iv;       // stored as int32
    float fv = *(const float*)p;              // stored as float32
    return (int)fv;
}

__global__ __launch_bounds__(256) void epilogue_kernel(
    const float* __restrict__ kmat, const int* __restrict__ labels,
    const void* __restrict__ ptr_in,
    float* __restrict__ cont_labels, float* __restrict__ new_queue,
    float* __restrict__ new_qp, float* __restrict__ new_ptr_out)
{
    const int ptr = load_ptr_val(ptr_in);
    int ptrc = ptr; if (ptrc < 0) ptrc = 0; if (ptrc > QQ - BB) ptrc = QQ - BB; // dynamic_update_slice clamp
    const int i = blockIdx.x * blockDim.x + threadIdx.x;

    const int NF4 = BB * DD / 4;          // 131072 float4
    if (i < NF4) {
        const int rowf4 = DD / 4;         // 32
        int r = i / rowf4, c4 = i % rowf4;
        float4 v = ((const float4*)kmat)[i];
        ((float4*)new_queue)[(size_t)(ptrc + r) * rowf4 + c4] = v;
    }
    if (i < BB) {
        float lab = (float)labels[i];
        cont_labels[i] = lab;
        cont_labels[BB + i] = lab;
        new_qp[ptrc + i] = lab;
    }
    if (i == 0) new_ptr_out[0] = (float)((ptr + BB) % QQ);
}

// ---------------------------------------------------------------------------
extern "C" void kernel_launch(void* const* d_in, const int* in_sizes, int n_in,
                              void* d_out, int out_size)
{
    const float* q       = (const float*)d_in[0];
    const float* k       = (const float*)d_in[1];
    const float* logits  = (const float*)d_in[2];
    const float* plabel  = (const float*)d_in[3];
    const float* protos  = (const float*)d_in[4];
    const float* queue   = (const float*)d_in[5];
    const float* queuep  = (const float*)d_in[6];
    const void*  ptr_in  = d_in[7];

    float* out = (float*)d_out;
    float* out_classfy = out + OFF_CLASSFY;
    float* out_cluster = out + OFF_CLUSTER;
    float* out_contf   = out + OFF_CONTF;
    float* out_contl   = out + OFF_CONTL;
    float* out_proto   = out + OFF_PROTO;
    float* out_queue   = out + OFF_QUEUE;
    float* out_qp      = out + OFF_QP;
    float* out_ptr     = out + OFF_PTR;

    float* logits_prot;
    cudaGetSymbolAddress((void**)&logits_prot, g_logits);
    int* labels;
    cudaGetSymbolAddress((void**)&labels, g_labels);

    cudaStream_t s = 0;

    // bulk copies (independent of kernels except scatter overwrites)
    cudaMemcpyAsync(out_contf,                 q,      (size_t)BB * DD * 4, cudaMemcpyDeviceToDevice, s);
    cudaMemcpyAsync(out_contf + (size_t)BB*DD, k,      (size_t)BB * DD * 4, cudaMemcpyDeviceToDevice, s);
    cudaMemcpyAsync(out_contf + (size_t)2*BB*DD, queue,(size_t)QQ * DD * 4, cudaMemcpyDeviceToDevice, s);
    cudaMemcpyAsync(out_queue, queue,                  (size_t)QQ * DD * 4, cudaMemcpyDeviceToDevice, s);
    cudaMemcpyAsync(out_qp, queuep,                    (size_t)QQ * 4,      cudaMemcpyDeviceToDevice, s);
    cudaMemcpyAsync(out_contl + 2*BB, queuep,          (size_t)QQ * 4,      cudaMemcpyDeviceToDevice, s);

    // 1) classfy softmax + pseudo labels
    classfy_kernel<<<BB, 256, 0, s>>>(logits, plabel, out_classfy, labels);

    // 2) cluster logits GEMM -> scratch
    dim3 ggrid((CC + GBN - 1) / GBN, BB / GBM);
    gemm_kernel<<<ggrid, 256, 0, s>>>(q, protos, logits_prot);

    // 3) cluster softmax
    cluster_softmax_kernel<<<BB, 256, 0, s>>>(logits_prot, out_cluster);

    // 4) epilogue scatter (needs labels + base queue copies; stream-ordered)
    {
        int nthreads = BB * DD / 4;  // 131072
        epilogue_kernel<<<(nthreads + 255) / 256, 256, 0, s>>>(
            k, labels, ptr_in, out_contl, out_queue, out_qp, out_ptr);
    }

    // 5) prototype EMA update
    proto_kernel<<<CC, 128, 0, s>>>(q, protos, labels, out_proto);
}

// round 2
// speedup vs baseline: 1.7367x; 1.7367x over previous
#include <cuda_runtime.h>
#include <cuda_bf16.h>
#include <math.h>
#include <stdint.h>

// Problem constants
#define BB 4096     // batch
#define CC 1000     // classes
#define DD 128      // feature dim
#define QQ 65536    // queue length
#define PROTO_M 0.99f

// ---- output layout (flat float32 concat, reference return order) ----
static const size_t OFF_CLASSFY = 0;
static const size_t OFF_CLUSTER = (size_t)BB * CC;
static const size_t OFF_CONTF   = OFF_CLUSTER + (size_t)BB * CC;
static const size_t OFF_CONTL   = OFF_CONTF + (size_t)(2 * BB + QQ) * DD;
static const size_t OFF_PROTO   = OFF_CONTL + (size_t)(2 * BB + QQ);
static const size_t OFF_QUEUE   = OFF_PROTO + (size_t)CC * DD;
static const size_t OFF_QP      = OFF_QUEUE + (size_t)QQ * DD;
static const size_t OFF_PTR     = OFF_QP + (size_t)QQ;

// scratch (no allocations allowed -> device globals)
__device__ float g_logits[(size_t)BB * CC];
__device__ int   g_labels[BB];

// ---------------------------------------------------------------------------
// Kernel 1: classfy softmax + argmax(softmax * plabel)
// ---------------------------------------------------------------------------
__global__ __launch_bounds__(256) void classfy_kernel(
    const float* __restrict__ logits, const float* __restrict__ plabel,
    float* __restrict__ out, int* __restrict__ labels)
{
    const int b = blockIdx.x;
    const int tid = threadIdx.x;
    const float* row = logits + (size_t)b * CC;
    const float* prow = plabel + (size_t)b * CC;
    float* orow = out + (size_t)b * CC;

    float l[4];
    float mx = -1e30f;
#pragma unroll
    for (int j = 0; j < 4; j++) {
        int c = j * 256 + tid;
        l[j] = (c < CC) ? row[c] : -1e30f;
        mx = fmaxf(mx, l[j]);
    }
    __shared__ float s0[8];
    __shared__ float s1[8];
    __shared__ float sv[8];
    __shared__ int   si[8];
#pragma unroll
    for (int o = 16; o; o >>= 1) mx = fmaxf(mx, __shfl_xor_sync(0xffffffffu, mx, o));
    if ((tid & 31) == 0) s0[tid >> 5] = mx;
    __syncthreads();
    if (tid < 32) {
        float v = (tid < 8) ? s0[tid] : -1e30f;
#pragma unroll
        for (int o = 4; o; o >>= 1) v = fmaxf(v, __shfl_xor_sync(0xffffffffu, v, o));
        if (tid == 0) s0[0] = v;
    }
    __syncthreads();
    mx = s0[0];

    float e[4];
    float sum = 0.f;
#pragma unroll
    for (int j = 0; j < 4; j++) { e[j] = __expf(l[j] - mx); sum += e[j]; }
#pragma unroll
    for (int o = 16; o; o >>= 1) sum += __shfl_xor_sync(0xffffffffu, sum, o);
    if ((tid & 31) == 0) s1[tid >> 5] = sum;
    __syncthreads();
    if (tid < 32) {
        float v = (tid < 8) ? s1[tid] : 0.f;
#pragma unroll
        for (int o = 4; o; o >>= 1) v += __shfl_xor_sync(0xffffffffu, v, o);
        if (tid == 0) s1[0] = v;
    }
    __syncthreads();
    const float inv = 1.0f / s1[0];

    float bv = -1.0f;
    int bi = 0x7fffffff;
#pragma unroll
    for (int j = 0; j < 4; j++) {
        int c = j * 256 + tid;
        if (c < CC) {
            float o = e[j] * inv;
            orow[c] = o;
            float v = o * prow[c];
            if (v > bv) { bv = v; bi = c; }
        }
    }
#pragma unroll
    for (int o = 16; o; o >>= 1) {
        float ov = __shfl_xor_sync(0xffffffffu, bv, o);
        int   oi = __shfl_xor_sync(0xffffffffu, bi, o);
        if (ov > bv || (ov == bv && oi < bi)) { bv = ov; bi = oi; }
    }
    if ((tid & 31) == 0) { sv[tid >> 5] = bv; si[tid >> 5] = bi; }
    __syncthreads();
    if (tid < 32) {
        float v = (tid < 8) ? sv[tid] : -1.0f;
        int   i = (tid < 8) ? si[tid] : 0x7fffffff;
#pragma unroll
        for (int o = 4; o; o >>= 1) {
            float ov = __shfl_xor_sync(0xffffffffu, v, o);
            int   oi = __shfl_xor_sync(0xffffffffu, i, o);
            if (ov > v || (ov == v && oi < i)) { v = ov; i = oi; }
        }
        if (tid == 0) labels[b] = i;
    }
}

// ---------------------------------------------------------------------------
// Kernel 2: logits = q @ protos^T with tf32 tensor cores
// BM=64, BN=64, K=128 in two 64-wide slices. 256 threads = 8 warps (2m x 4n).
// mma.sync.aligned.m16n8k8.row.col.f32.tf32.tf32.f32
// ---------------------------------------------------------------------------
__device__ __forceinline__ uint32_t f32_to_tf32(float f)
{
    uint32_t r;
    asm volatile("cvt.rna.tf32.f32 %0, %1;" : "=r"(r) : "f"(f));
    return r;
}

__device__ __forceinline__ void mma_tf32(float c[4],
    uint32_t a0, uint32_t a1, uint32_t a2, uint32_t a3,
    uint32_t b0, uint32_t b1)
{
    asm volatile(
        "mma.sync.aligned.m16n8k8.row.col.f32.tf32.tf32.f32 "
        "{%0,%1,%2,%3}, {%4,%5,%6,%7}, {%8,%9}, {%0,%1,%2,%3};"
        : "+f"(c[0]), "+f"(c[1]), "+f"(c[2]), "+f"(c[3])
        : "r"(a0), "r"(a1), "r"(a2), "r"(a3), "r"(b0), "r"(b1));
}

#define TBM 64
#define TBN 64
#define TBK 64
__global__ __launch_bounds__(256) void gemm_tf32_kernel(
    const float* __restrict__ Aq, const float* __restrict__ Bp,
    float* __restrict__ Cout)
{
    __shared__ uint32_t As[TBM][TBK + 4];   // pad 4: frag loads hit all 32 banks
    __shared__ uint32_t Bs[TBN][TBK + 4];

    const int tid  = threadIdx.x;
    const int w    = tid >> 5;
    const int lane = tid & 31;
    const int wm   = w & 1;       // 0..1  -> 32 rows each
    const int wn   = w >> 1;      // 0..3  -> 16 cols each
    const int g    = lane >> 2;   // 0..7
    const int tig  = lane & 3;    // 0..3
    const int m0   = blockIdx.y * TBM;
    const int n0   = blockIdx.x * TBN;

    float c[2][2][4];
#pragma unroll
    for (int mt = 0; mt < 2; mt++)
#pragma unroll
        for (int nt = 0; nt < 2; nt++)
#pragma unroll
            for (int i = 0; i < 4; i++) c[mt][nt][i] = 0.f;

    for (int kt = 0; kt < 2; kt++) {
        const int kk = kt * TBK;
        // load A slice 64x64 and B slice 64x64 (f4 = 16 cols per row => 1024 f4 each)
#pragma unroll
        for (int p = 0; p < 4; p++) {
            int idx = p * 256 + tid;      // 0..1023
            int r  = idx >> 4;
            int c4 = (idx & 15) * 4;
            float4 va = *(const float4*)(Aq + (size_t)(m0 + r) * DD + kk + c4);
            As[r][c4 + 0] = f32_to_tf32(va.x);
            As[r][c4 + 1] = f32_to_tf32(va.y);
            As[r][c4 + 2] = f32_to_tf32(va.z);
            As[r][c4 + 3] = f32_to_tf32(va.w);
            int n = n0 + r;
            float4 vb = make_float4(0.f, 0.f, 0.f, 0.f);
            if (n < CC) vb = *(const float4*)(Bp + (size_t)n * DD + kk + c4);
            Bs[r][c4 + 0] = f32_to_tf32(vb.x);
            Bs[r][c4 + 1] = f32_to_tf32(vb.y);
            Bs[r][c4 + 2] = f32_to_tf32(vb.z);
            Bs[r][c4 + 3] = f32_to_tf32(vb.w);
        }
        __syncthreads();

#pragma unroll
        for (int ks = 0; ks < TBK / 8; ks++) {
            const int k0 = ks * 8;
            uint32_t a[2][4], bfr[2][2];
#pragma unroll
            for (int mt = 0; mt < 2; mt++) {
                int rb = wm * 32 + mt * 16 + g;
                a[mt][0] = As[rb][k0 + tig];
                a[mt][1] = As[rb + 8][k0 + tig];
                a[mt][2] = As[rb][k0 + tig + 4];
                a[mt][3] = As[rb + 8][k0 + tig + 4];
            }
#pragma unroll
            for (int nt = 0; nt < 2; nt++) {
                int cb = wn * 16 + nt * 8 + g;
                bfr[nt][0] = Bs[cb][k0 + tig];
                bfr[nt][1] = Bs[cb][k0 + tig + 4];
            }
#pragma unroll
            for (int mt = 0; mt < 2; mt++)
#pragma unroll
                for (int nt = 0; nt < 2; nt++)
                    mma_tf32(c[mt][nt], a[mt][0], a[mt][1], a[mt][2], a[mt][3],
                             bfr[nt][0], bfr[nt][1]);
        }
        __syncthreads();
    }

    // store: c0/c1 -> (row g, cols 2tig,2tig+1), c2/c3 -> row g+8
#pragma unroll
    for (int mt = 0; mt < 2; mt++) {
#pragma unroll
        for (int nt = 0; nt < 2; nt++) {
            int m = m0 + wm * 32 + mt * 16 + g;
            int n = n0 + wn * 16 + nt * 8 + 2 * tig;
            if (n < CC) {
                *(float2*)(Cout + (size_t)m * CC + n) =
                    make_float2(c[mt][nt][0], c[mt][nt][1]);
                *(float2*)(Cout + (size_t)(m + 8) * CC + n) =
                    make_float2(c[mt][nt][2], c[mt][nt][3]);
            }
        }
    }
}

// ---------------------------------------------------------------------------
// Kernel 3: cluster softmax (row softmax of scratch logits)
// ---------------------------------------------------------------------------
__global__ __launch_bounds__(256) void cluster_softmax_kernel(
    const float* __restrict__ logits, float* __restrict__ out)
{
    const int b = blockIdx.x;
    const int tid = threadIdx.x;
    const float* row = logits + (size_t)b * CC;
    float* orow = out + (size_t)b * CC;

    float l[4];
    float mx = -1e30f;
#pragma unroll
    for (int j = 0; j < 4; j++) {
        int c = j * 256 + tid;
        l[j] = (c < CC) ? row[c] : -1e30f;
        mx = fmaxf(mx, l[j]);
    }
    __shared__ float s0[8];
    __shared__ float s1[8];
#pragma unroll
    for (int o = 16; o; o >>= 1) mx = fmaxf(mx, __shfl_xor_sync(0xffffffffu, mx, o));
    if ((tid & 31) == 0) s0[tid >> 5] = mx;
    __syncthreads();
    if (tid < 32) {
        float v = (tid < 8) ? s0[tid] : -1e30f;
#pragma unroll
        for (int o = 4; o; o >>= 1) v = fmaxf(v, __shfl_xor_sync(0xffffffffu, v, o));
        if (tid == 0) s0[0] = v;
    }
    __syncthreads();
    mx = s0[0];

    float e[4];
    float sum = 0.f;
#pragma unroll
    for (int j = 0; j < 4; j++) { e[j] = __expf(l[j] - mx); sum += e[j]; }
#pragma unroll
    for (int o = 16; o; o >>= 1) sum += __shfl_xor_sync(0xffffffffu, sum, o);
    if ((tid & 31) == 0) s1[tid >> 5] = sum;
    __syncthreads();
    if (tid < 32) {
        float v = (tid < 8) ? s1[tid] : 0.f;
#pragma unroll
        for (int o = 4; o; o >>= 1) v += __shfl_xor_sync(0xffffffffu, v, o);
        if (tid == 0) s1[0] = v;
    }
    __syncthreads();
    const float inv = 1.0f / s1[0];
#pragma unroll
    for (int j = 0; j < 4; j++) {
        int c = j * 256 + tid;
        if (c < CC) orow[c] = e[j] * inv;
    }
}

// ---------------------------------------------------------------------------
// Kernel 4: prototype scatter-EMA + l2norm. One block (128 thr) per class.
// ---------------------------------------------------------------------------
__global__ __launch_bounds__(128) void proto_kernel(
    const float* __restrict__ q, const float* __restrict__ protos,
    const int* __restrict__ labels, float* __restrict__ out)
{
    const int c = blockIdx.x;
    const int t = threadIdx.x;

    __shared__ int counts[128];
    __shared__ int offs[128];
    __shared__ int idxbuf[BB];
    __shared__ int total_s;
    __shared__ float ws[4];

    const int base = t * 32;
    int cnt = 0;
#pragma unroll 8
    for (int j = 0; j < 32; j++) if (__ldg(&labels[base + j]) == c) cnt++;
    counts[t] = cnt;
    __syncthreads();
    if (t == 0) {
        int run = 0;
        for (int u = 0; u < 128; u++) { offs[u] = run; run += counts[u]; }
        total_s = run;
    }
    __syncthreads();
    int w = offs[t];
#pragma unroll 8
    for (int j = 0; j < 32; j++) {
        int i = base + j;
        if (__ldg(&labels[i]) == c) idxbuf[w++] = i;
    }
    __syncthreads();
    const int total = total_s;

    float acc = protos[(size_t)c * DD + t];
    for (int j = 0; j < total; j++) {
        acc = PROTO_M * acc + (1.0f - PROTO_M) * q[(size_t)idxbuf[j] * DD + t];
    }
    float s = acc * acc;
#pragma unroll
    for (int o = 16; o; o >>= 1) s += __shfl_xor_sync(0xffffffffu, s, o);
    if ((t & 31) == 0) ws[t >> 5] = s;
    __syncthreads();
    float tot = ws[0] + ws[1] + ws[2] + ws[3];
    float nrm = sqrtf(tot);
    float inv = 1.0f / fmaxf(nrm, 1e-12f);
    out[(size_t)c * DD + t] = acc * inv;
}

// ---------------------------------------------------------------------------
// Kernel 5: fused bulk duplication (replaces 6 memcpys; queue read ONCE)
// ---------------------------------------------------------------------------
__global__ __launch_bounds__(256) void bulkdup_kernel(
    const float4* __restrict__ q4, const float4* __restrict__ k4,
    const float4* __restrict__ queue4, const float* __restrict__ qp,
    float4* __restrict__ contf4, float4* __restrict__ outq4,
    float* __restrict__ outqp, float* __restrict__ contl)
{
    const int i = blockIdx.x * blockDim.x + threadIdx.x;
    const int NQ4 = QQ * DD / 4;   // 2,097,152
    const int NB4 = BB * DD / 4;   // 131,072
    if (i < NQ4) {
        float4 v = queue4[i];
        contf4[2 * NB4 + i] = v;   // cont_features queue part
        outq4[i] = v;              // new_queue base
    }
    if (i < NB4) {
        contf4[i] = q4[i];
        contf4[NB4 + i] = k4[i];
    }
    if (i < QQ) {
        float v = qp[i];
        outqp[i] = v;              // new_queue_pseudo base
        contl[2 * BB + i] = v;     // cont_labels tail
    }
}

// ---------------------------------------------------------------------------
// Kernel 6: epilogue scatter — k rows into new_queue at ptr, labels out
// ---------------------------------------------------------------------------
__device__ __forceinline__ int load_ptr_val(const void* p)
{
    int iv = *(const int*)p;
    if (iv >= 0 && iv <= QQ) return iv;       // stored as int32
    float fv = *(const float*)p;              // stored as float32
    return (int)fv;
}

__global__ __launch_bounds__(256) void epilogue_kernel(
    const float* __restrict__ kmat, const int* __restrict__ labels,
    const void* __restrict__ ptr_in,
    float* __restrict__ cont_labels, float* __restrict__ new_queue,
    float* __restrict__ new_qp, float* __restrict__ new_ptr_out)
{
    const int ptr = load_ptr_val(ptr_in);
    int ptrc = ptr; if (ptrc < 0) ptrc = 0; if (ptrc > QQ - BB) ptrc = QQ - BB;
    const int i = blockIdx.x * blockDim.x + threadIdx.x;

    const int NF4 = BB * DD / 4;
    if (i < NF4) {
        const int rowf4 = DD / 4;
        int r = i / rowf4, c4 = i % rowf4;
        float4 v = ((const float4*)kmat)[i];
        ((float4*)new_queue)[(size_t)(ptrc + r) * rowf4 + c4] = v;
    }
    if (i < BB) {
        float lab = (float)labels[i];
        cont_labels[i] = lab;
        cont_labels[BB + i] = lab;
        new_qp[ptrc + i] = lab;
    }
    if (i == 0) new_ptr_out[0] = (float)((ptr + BB) % QQ);
}

// ---------------------------------------------------------------------------
extern "C" void kernel_launch(void* const* d_in, const int* in_sizes, int n_in,
                              void* d_out, int out_size)
{
    const float* q       = (const float*)d_in[0];
    const float* k       = (const float*)d_in[1];
    const float* logits  = (const float*)d_in[2];
    const float* plabel  = (const float*)d_in[3];
    const float* protos  = (const float*)d_in[4];
    const float* queue   = (const float*)d_in[5];
    const float* queuep  = (const float*)d_in[6];
    const void*  ptr_in  = d_in[7];

    float* out = (float*)d_out;
    float* out_classfy = out + OFF_CLASSFY;
    float* out_cluster = out + OFF_CLUSTER;
    float* out_contf   = out + OFF_CONTF;
    float* out_contl   = out + OFF_CONTL;
    float* out_proto   = out + OFF_PROTO;
    float* out_queue   = out + OFF_QUEUE;
    float* out_qp      = out + OFF_QP;
    float* out_ptr     = out + OFF_PTR;

    float* logits_prot;
    cudaGetSymbolAddress((void**)&logits_prot, g_logits);
    int* labels;
    cudaGetSymbolAddress((void**)&labels, g_labels);

    cudaStream_t s = 0;

    // 1) classfy softmax + pseudo labels
    classfy_kernel<<<BB, 256, 0, s>>>(logits, plabel, out_classfy, labels);

    // 2) cluster logits GEMM (tf32 tensor cores) -> scratch
    dim3 ggrid((CC + TBN - 1) / TBN, BB / TBM);   // 16 x 64
    gemm_tf32_kernel<<<ggrid, 256, 0, s>>>(q, protos, logits_prot);

    // 3) cluster softmax
    cluster_softmax_kernel<<<BB, 256, 0, s>>>(logits_prot, out_cluster);

    // 4) fused bulk copies
    {
        int nthreads = QQ * DD / 4;   // 2,097,152
        bulkdup_kernel<<<(nthreads + 255) / 256, 256, 0, s>>>(
            (const float4*)q, (const float4*)k, (const float4*)queue, queuep,
            (float4*)out_contf, (float4*)out_queue, out_qp, out_contl);
    }

    // 5) epilogue scatter (needs labels + bulkdup)
    {
        int nthreads = BB * DD / 4;
        epilogue_kernel<<<(nthreads + 255) / 256, 256, 0, s>>>(
            k, labels, ptr_in, out_contl, out_queue, out_qp, out_ptr);
    }

    // 6) prototype EMA update
    proto_kernel<<<CC, 128, 0, s>>>(q, protos, labels, out_proto);
}